// round 7
// baseline (speedup 1.0000x reference)
#include <cuda_runtime.h>

#define G_ 4
#define T_ 2048
#define E_ 8
#define D_ 1024
#define C_ 2048
#define NTOK (G_ * T_)

#define NB 148
#define THREADS 1024
#define FILLW 26                      // warps 0..25 fill; warps 26..31 special
#define NROUTERW (NB * 6)             // 888 router warps
#define NTOPKB 32                     // blocks 0..31 own one (g,e) each
// fill participants: 26*148 + 6*(148-32) = 3848 + 696 = 4544
#define NFILL_UNITS (FILLW * NB + 6 * (NB - NTOPKB))

#define NTOT ((long long)G_ * T_ * E_ * C_)        // 134217728
#define N4 ((long long)(2 * NTOT / 4))             // 67108864 float4
#define CHUNK_F4 2048                               // 32 KB per chunk
#define NCHUNKS ((int)(N4 / CHUNK_F4))              // 32768

__device__ float g_probs[G_ * E_ * T_];   // expert-major probs
__device__ float g_zt[NTOK];              // per-token z partials
__device__ int   g_router_done;
__device__ int   g_fill_done;
__device__ int   g_chunk;

__global__ void init_kernel() {
    g_router_done = 0;
    g_fill_done = 0;
    g_chunk = 0;
}

__device__ __forceinline__ void spin_ge(volatile int* p, int target) {
    while (*p < target) __nanosleep(64);
}

__device__ __forceinline__ void bar192() {
    asm volatile("bar.sync 1, 192;" ::: "memory");
}

// Per-warp work-stealing zero fill (no cross-warp synchronization at all).
__device__ __forceinline__ void warp_fill(float4* __restrict__ out4, int lane) {
    const float4 z = make_float4(0.f, 0.f, 0.f, 0.f);
    for (;;) {
        int c = 0;
        if (lane == 0) c = atomicAdd(&g_chunk, 1);
        c = __shfl_sync(0xffffffffu, c, 0);
        if (c >= NCHUNKS) break;
        long long base = (long long)c * CHUNK_F4 + lane;
        #pragma unroll 8
        for (int i = 0; i < CHUNK_F4 / 32; i++)
            out4[base + i * 32] = z;
    }
    __threadfence();
    if (lane == 0) atomicAdd(&g_fill_done, 1);
}

__global__ void __launch_bounds__(THREADS, 1)
fused_kernel(const float* __restrict__ x,
             const float* __restrict__ W,
             const float* __restrict__ b,
             float* __restrict__ out) {
    __shared__ __align__(16) union {
        struct { float sW[E_ * D_]; float sb[E_]; } r;              // 32 KB
        struct { unsigned long long keys[T_]; float red[256]; } t;  // 17 KB
    } sm;

    float4* out4 = reinterpret_cast<float4*>(out);
    int warp = threadIdx.x >> 5;
    int lane = threadIdx.x & 31;
    int B = blockIdx.x;

    // ------------------------- fill warps: store from t = 0 -------------------------
    if (warp < FILLW) {
        warp_fill(out4, lane);
        return;
    }

    // ------------------------- special warps (26..31): router -------------------------
    int tid192 = (warp - FILLW) * 32 + lane;     // 0..191

    for (int i = tid192; i < E_ * D_ / 4; i += 192)
        reinterpret_cast<float4*>(sm.r.sW)[i] = reinterpret_cast<const float4*>(W)[i];
    if (tid192 < E_) sm.r.sb[tid192] = b[tid192];
    bar192();

    int rw = B * 6 + (warp - FILLW);             // global router warp id 0..887
    for (int token = rw; token < NTOK; token += NROUTERW) {
        int g = token / T_;
        int t = token % T_;
        const float4* x4 = reinterpret_cast<const float4*>(x + (long long)token * D_);

        float acc[E_];
        #pragma unroll
        for (int e = 0; e < E_; e++) acc[e] = 0.f;

        #pragma unroll
        for (int i = 0; i < D_ / (32 * 4); i++) {    // 8 iterations
            int d4 = i * 32 + lane;
            float4 xv = x4[d4];
            #pragma unroll
            for (int e = 0; e < E_; e++) {
                float4 wv = reinterpret_cast<const float4*>(sm.r.sW + e * D_)[d4];
                acc[e] += xv.x * wv.x + xv.y * wv.y + xv.z * wv.z + xv.w * wv.w;
            }
        }
        #pragma unroll
        for (int o = 16; o > 0; o >>= 1)
            #pragma unroll
            for (int e = 0; e < E_; e++)
                acc[e] += __shfl_xor_sync(0xffffffffu, acc[e], o);

        float m = -1e30f;
        #pragma unroll
        for (int e = 0; e < E_; e++) { acc[e] += sm.r.sb[e]; m = fmaxf(m, acc[e]); }
        float ex[E_], s = 0.f;
        #pragma unroll
        for (int e = 0; e < E_; e++) { ex[e] = expf(acc[e] - m); s += ex[e]; }
        float inv = 1.f / s;
        float lse = m + logf(s);

        if (lane < E_)
            g_probs[(g * E_ + lane) * T_ + t] = ex[lane] * inv;
        if (lane == 0) {
            float zt = 0.f;
            #pragma unroll
            for (int e = 0; e < E_; e++) {
                float ls = acc[e] - lse;
                zt += ls * ls;
            }
            g_zt[token] = zt;
        }
    }
    __threadfence();
    if (lane == 0) atomicAdd(&g_router_done, 1);

    // ---------------- non-topk blocks: router warps join the fill ----------------
    if (B >= NTOPKB) {
        warp_fill(out4, lane);
        return;
    }

    // ---------------- topk blocks (0..31): sort -> wait fill -> scatter ----------------
    int ge = B;                // 0..31
    int e = ge & 7;
    int g = ge >> 3;

    if (tid192 == 0) spin_ge(&g_router_done, NROUTERW);
    bar192();                  // also guarantees all 6 warps stopped reading sW
    __threadfence();

    const float* p = g_probs + (long long)ge * T_;
    for (int t = tid192; t < T_; t += 192) {
        unsigned int pb = __float_as_uint(p[t]);   // probs > 0 -> bits monotonic
        sm.t.keys[t] = ((unsigned long long)pb << 32) | (unsigned int)(~t);
    }
    bar192();

    // bitonic sort, descending: prob desc, index asc on ties (matches lax.top_k)
    for (int k = 2; k <= T_; k <<= 1) {
        for (int j = k >> 1; j > 0; j >>= 1) {
            for (int i = tid192; i < T_; i += 192) {
                int ixj = i ^ j;
                if (ixj > i) {
                    bool desc = ((i & k) == 0);
                    unsigned long long a = sm.t.keys[i], c = sm.t.keys[ixj];
                    if (desc ? (a < c) : (a > c)) { sm.t.keys[i] = c; sm.t.keys[ixj] = a; }
                }
            }
            bar192();
        }
    }

    // block 0: z-loss reduction over 192 partials, padded to 256 so the
    // tree is power-of-two (192-wide tree dropped red[2] => 1/3 sum loss).
    if (ge == 0) {
        float acc = 0.f;
        for (int i = tid192; i < NTOK; i += 192)
            acc += g_zt[i];
        sm.t.red[tid192] = acc;
        if (tid192 < 64) sm.t.red[192 + tid192] = 0.f;
        bar192();
        for (int o = 128; o > 0; o >>= 1) {
            if (tid192 < o) sm.t.red[tid192] += sm.t.red[tid192 + o];
            bar192();
        }
        if (tid192 == 0)
            out[2 * NTOT] = sm.t.red[0] / (float)(G_ * T_ * E_);
    }

    // wait for the entire fill, then scatter the nonzeros
    if (tid192 == 0) spin_ge(&g_fill_done, NFILL_UNITS);
    bar192();
    __threadfence();

    const int caps[E_] = {512, 512, 256, 256, 128, 128, 128, 128};
    int cap = caps[e];
    for (int r = tid192; r < cap; r += 192) {
        unsigned long long key = sm.t.keys[r];
        float gate = __uint_as_float((unsigned int)(key >> 32));
        int tok = (int)(~(unsigned int)(key & 0xffffffffu));
        long long off = (((long long)g * T_ + tok) * E_ + e) * C_ + r;
        out[off]        = 1.0f;   // dispatch_mask
        out[NTOT + off] = gate;   // combine_array
    }
}

extern "C" void kernel_launch(void* const* d_in, const int* in_sizes, int n_in,
                              void* d_out, int out_size) {
    const float* x = (const float*)d_in[0];   // token_inputs [G,T,D]
    const float* W = (const float*)d_in[1];   // [E,D]
    const float* b = (const float*)d_in[2];   // [E]
    float* out = (float*)d_out;

    init_kernel<<<1, 1>>>();
    fused_kernel<<<NB, THREADS>>>(x, W, b, out);
}